// round 1
// baseline (speedup 1.0000x reference)
#include <cuda_runtime.h>
#include <math.h>

// Problem constants
#define Bq 8
#define Pq 64
#define Vq 8
#define Lq 1024
#define Dq 256
#define NCHUNK 32
#define CLEN 32          // NCHUNK * CLEN == Lq

// Scratch (static device globals; no allocation in kernel_launch)
__device__ float g_pr[Bq * NCHUNK * Dq];          // chunk partial sums (real)
__device__ float g_pi[Bq * NCHUNK * Dq];          // chunk partial sums (imag)
__device__ float g_ycat[Bq * Pq * 2 * Dq];        // [b, p, k] k<256: y_fwd, k>=256: y_bwd
__device__ float g_Wt[2 * Dq * Dq];               // W^T, [k][j] layout for coalesced GEMM

// ---------------------------------------------------------------------------
// Kernel 0: transpose proj_W [D, 2D] -> Wt [2D, D]  (Wt[k][j] = W[j][k])
// ---------------------------------------------------------------------------
__global__ void k_transpose(const float* __restrict__ W) {
    int k = blockIdx.x;      // 0..511
    int j = threadIdx.x;     // 0..255
    g_Wt[k * Dq + j] = W[j * (2 * Dq) + k];
}

// ---------------------------------------------------------------------------
// Kernel 1: per-(b, chunk, d) compute Σ_{i<CLEN} λ_b^i * x̄[chunk*CLEN + i]
// where x̄[s] = mean_V(ts_embeds[b, s, :, d]) + signal_emb[d].
// This is the DRAM-bound kernel (reads all 67 MB of ts_embeds once).
// ---------------------------------------------------------------------------
__global__ void k_chunks(const float* __restrict__ ts,
                         const float* __restrict__ bnu,
                         const float* __restrict__ btheta,
                         const float* __restrict__ sig) {
    const int d = threadIdx.x;
    const int c = blockIdx.x;     // chunk
    const int b = blockIdx.y;     // batch

    const float r  = expf(-expf(bnu[d]));
    float s_, c_;
    sincosf(btheta[d], &s_, &c_);
    const float lr = r * c_;
    const float li = r * s_;
    const float sg = sig[d];

    const float* base = ts + ((size_t)b * Lq + (size_t)c * CLEN) * (Vq * Dq) + d;

    float wr = 1.f, wi = 0.f, ar = 0.f, ai = 0.f;
#pragma unroll 8
    for (int i = 0; i < CLEN; i++) {
        const float* p = base + (size_t)i * (Vq * Dq);
        float xm = __ldg(p);
#pragma unroll
        for (int v = 1; v < Vq; v++) xm += __ldg(p + v * Dq);
        xm = xm * 0.125f + sg;
        ar = fmaf(wr, xm, ar);
        ai = fmaf(wi, xm, ai);
        // w *= lam
        float t0 = wr * lr - wi * li;
        wi = fmaf(wr, li, wi * lr);
        wr = t0;
    }
    g_pr[(b * NCHUNK + c) * Dq + d] = ar;
    g_pi[(b * NCHUNK + c) * Dq + d] = ai;
}

// ---------------------------------------------------------------------------
// Kernel 2: per-(b, d): 64-step fwd scan over prefix, combine chunk partials
// into tail sum S, 64-step bwd scan seeded with S. Emit y_fwd/y_bwd.
// ---------------------------------------------------------------------------
__global__ void k_scan(const float* __restrict__ mem,
                       const float* __restrict__ fnu,
                       const float* __restrict__ ftheta,
                       const float* __restrict__ fgr,
                       const float* __restrict__ fgi,
                       const float* __restrict__ bnu,
                       const float* __restrict__ btheta,
                       const float* __restrict__ bgr,
                       const float* __restrict__ bgi,
                       const float* __restrict__ prefix) {
    const int d = threadIdx.x;
    const int b = blockIdx.x;

    // x[t] = memory + prefix, t in [0, P)
    float x[Pq];
    const float pre = prefix[d];
#pragma unroll
    for (int t = 0; t < Pq; t++)
        x[t] = mem[(b * Pq + t) * Dq + d] + pre;

    float* yc = g_ycat + (size_t)(b * Pq) * (2 * Dq);

    // ---- forward scan: h = lam_f*h + x[t];  y_fwd[t] = Re(g_f * h)
    {
        const float rf = expf(-expf(fnu[d]));
        float sf, cf;
        sincosf(ftheta[d], &sf, &cf);
        const float lfr = rf * cf, lfi = rf * sf;
        const float gfr = fgr[d], gfi = fgi[d];
        float hr = 0.f, hi = 0.f;
#pragma unroll
        for (int t = 0; t < Pq; t++) {
            float nr = fmaf(lfr, hr, fmaf(-lfi, hi, x[t]));
            float ni = fmaf(lfr, hi, lfi * hr);
            hr = nr; hi = ni;
            yc[t * (2 * Dq) + d] = gfr * hr - gfi * hi;
        }
    }

    // ---- backward: tail sum S = Σ_c lam_b^{CLEN*c} * partial_c
    const float ab = expf(bnu[d]);
    const float thb = btheta[d];
    const float rb = expf(-ab);
    float sb, cb;
    sincosf(thb, &sb, &cb);
    const float lbr = rb * cb, lbi = rb * sb;
    const float gbr = bgr[d], gbi = bgi[d];

    float Sr = 0.f, Si = 0.f;
#pragma unroll
    for (int c = 0; c < NCHUNK; c++) {
        const float t = (float)(CLEN * c);
        const float e = expf(-t * ab);       // |lam_b|^{CLEN*c}
        float sw, cw;
        sincosf(t * thb, &sw, &cw);
        const float wr = e * cw, wi = e * sw;
        const float pr = g_pr[(b * NCHUNK + c) * Dq + d];
        const float pi = g_pi[(b * NCHUNK + c) * Dq + d];
        Sr += wr * pr - wi * pi;
        Si += wr * pi + wi * pr;
    }

    // ---- backward scan seeded with S (state "beyond position P")
    float hr = Sr, hi = Si;
#pragma unroll
    for (int t = Pq - 1; t >= 0; t--) {
        float nr = fmaf(lbr, hr, fmaf(-lbi, hi, x[t]));
        float ni = fmaf(lbr, hi, lbi * hr);
        hr = nr; hi = ni;
        yc[t * (2 * Dq) + Dq + d] = gbr * hr - gbi * hi;
    }
}

// ---------------------------------------------------------------------------
// Kernel 3: projection. out[b,p,j] = Σ_k ycat[b,p,k] * W[j,k] + bias[j]
// Block = (4 p-rows, one b). Threads = j (256). Wt read coalesced from L2,
// y-tile staged in smem laid out [k][p] for float4 broadcast loads.
// ---------------------------------------------------------------------------
__global__ void k_proj(const float* __restrict__ bias, float* __restrict__ out) {
    __shared__ float ys[512 * 4];   // [k][p]
    const int j  = threadIdx.x;
    const int b  = blockIdx.y;
    const int p0 = blockIdx.x * 4;

    const float* src = g_ycat + (size_t)(b * Pq + p0) * (2 * Dq);
    for (int idx = j; idx < 4 * 512; idx += 256) {
        int p = idx >> 9;
        int k = idx & 511;
        ys[k * 4 + p] = src[p * 512 + k];
    }
    __syncthreads();

    const float bj = bias[j];
    float a0 = bj, a1 = bj, a2 = bj, a3 = bj;
#pragma unroll 8
    for (int k = 0; k < 512; k++) {
        const float w = g_Wt[k * Dq + j];
        const float4 y = *(const float4*)&ys[k * 4];
        a0 = fmaf(y.x, w, a0);
        a1 = fmaf(y.y, w, a1);
        a2 = fmaf(y.z, w, a2);
        a3 = fmaf(y.w, w, a3);
    }

    float* o = out + (size_t)(b * Pq + p0) * Dq + j;
    o[0 * Dq] = a0;
    o[1 * Dq] = a1;
    o[2 * Dq] = a2;
    o[3 * Dq] = a3;
}

// ---------------------------------------------------------------------------
extern "C" void kernel_launch(void* const* d_in, const int* in_sizes, int n_in,
                              void* d_out, int out_size) {
    const float* memory  = (const float*)d_in[0];
    const float* ts      = (const float*)d_in[1];
    const float* fnu     = (const float*)d_in[2];
    const float* ftheta  = (const float*)d_in[3];
    const float* fgr     = (const float*)d_in[4];
    const float* fgi     = (const float*)d_in[5];
    const float* bnu     = (const float*)d_in[6];
    const float* btheta  = (const float*)d_in[7];
    const float* bgr     = (const float*)d_in[8];
    const float* bgi     = (const float*)d_in[9];
    const float* projW   = (const float*)d_in[10];
    const float* projb   = (const float*)d_in[11];
    const float* prefix  = (const float*)d_in[12];
    const float* signal  = (const float*)d_in[13];
    float* out = (float*)d_out;

    k_transpose<<<2 * Dq, Dq>>>(projW);
    k_chunks<<<dim3(NCHUNK, Bq), Dq>>>(ts, bnu, btheta, signal);
    k_scan<<<Bq, Dq>>>(memory, fnu, ftheta, fgr, fgi,
                       bnu, btheta, bgr, bgi, prefix);
    k_proj<<<dim3(Pq / 4, Bq), Dq>>>(projb, out);
}

// round 2
// speedup vs baseline: 1.1882x; 1.1882x over previous
#include <cuda_runtime.h>
#include <math.h>

// Problem constants
#define Bq 8
#define Pq 64
#define Vq 8
#define Lq 1024
#define Dq 256
#define NCHUNK 32
#define CLEN 32          // NCHUNK * CLEN == Lq
#define KSPLIT 4
#define KSEG 128         // 512 / KSPLIT
#define RG 8             // rows per projection block

// Scratch (static device globals; no allocation in kernel_launch)
__device__ float g_pr[Bq * NCHUNK * Dq];          // chunk partial sums (real)
__device__ float g_pi[Bq * NCHUNK * Dq];          // chunk partial sums (imag)
__device__ float g_ycat[Bq * Pq * 2 * Dq];        // [b, p, k] k<256: y_fwd, k>=256: y_bwd
__device__ float g_Wt[2 * Dq * Dq];               // W^T, [k][j]
__device__ float g_part[Bq * KSPLIT * Pq * Dq];   // split-k partials

// ---------------------------------------------------------------------------
// Kernel 0: transpose proj_W [D, 2D] -> Wt [2D, D]
// ---------------------------------------------------------------------------
__global__ void k_transpose(const float* __restrict__ W) {
    int k = blockIdx.x;      // 0..511
    int j = threadIdx.x;     // 0..255
    g_Wt[k * Dq + j] = W[j * (2 * Dq) + k];
}

// ---------------------------------------------------------------------------
// Kernel 1: per-(b, chunk, d): Σ_{i<CLEN} λ_b^i * x̄[c*CLEN+i]
// x̄[s] = mean_V(ts_embeds[b,s,:,d]) + signal_emb[d].  DRAM-bound (67 MB).
// ---------------------------------------------------------------------------
__global__ void k_chunks(const float* __restrict__ ts,
                         const float* __restrict__ bnu,
                         const float* __restrict__ btheta,
                         const float* __restrict__ sig) {
    const int d = threadIdx.x;
    const int c = blockIdx.x;     // chunk
    const int b = blockIdx.y;     // batch

    const float r  = expf(-expf(bnu[d]));
    float s_, c_;
    sincosf(btheta[d], &s_, &c_);
    const float lr = r * c_;
    const float li = r * s_;
    const float sg = sig[d];

    const float* base = ts + ((size_t)b * Lq + (size_t)c * CLEN) * (Vq * Dq) + d;

    float wr = 1.f, wi = 0.f, ar = 0.f, ai = 0.f;
#pragma unroll 8
    for (int i = 0; i < CLEN; i++) {
        const float* p = base + (size_t)i * (Vq * Dq);
        float xm = __ldg(p);
#pragma unroll
        for (int v = 1; v < Vq; v++) xm += __ldg(p + v * Dq);
        xm = xm * 0.125f + sg;
        ar = fmaf(wr, xm, ar);
        ai = fmaf(wi, xm, ai);
        float t0 = wr * lr - wi * li;
        wi = fmaf(wr, li, wi * lr);
        wr = t0;
    }
    g_pr[(b * NCHUNK + c) * Dq + d] = ar;
    g_pi[(b * NCHUNK + c) * Dq + d] = ai;
}

// ---------------------------------------------------------------------------
// Kernel 2: per-(b, d): fwd scan (64 steps), tail-sum from chunk partials,
// bwd scan (64 steps). Emits y_fwd / y_bwd into g_ycat.
// ---------------------------------------------------------------------------
__global__ void k_scan(const float* __restrict__ mem,
                       const float* __restrict__ fnu,
                       const float* __restrict__ ftheta,
                       const float* __restrict__ fgr,
                       const float* __restrict__ fgi,
                       const float* __restrict__ bnu,
                       const float* __restrict__ btheta,
                       const float* __restrict__ bgr,
                       const float* __restrict__ bgi,
                       const float* __restrict__ prefix) {
    const int d = threadIdx.x;
    const int b = blockIdx.x;

    float x[Pq];
    const float pre = prefix[d];
#pragma unroll
    for (int t = 0; t < Pq; t++)
        x[t] = mem[(b * Pq + t) * Dq + d] + pre;

    float* yc = g_ycat + (size_t)(b * Pq) * (2 * Dq);

    // forward scan
    {
        const float rf = expf(-expf(fnu[d]));
        float sf, cf;
        sincosf(ftheta[d], &sf, &cf);
        const float lfr = rf * cf, lfi = rf * sf;
        const float gfr = fgr[d], gfi = fgi[d];
        float hr = 0.f, hi = 0.f;
#pragma unroll
        for (int t = 0; t < Pq; t++) {
            float nr = fmaf(lfr, hr, fmaf(-lfi, hi, x[t]));
            float ni = fmaf(lfr, hi, lfi * hr);
            hr = nr; hi = ni;
            yc[t * (2 * Dq) + d] = gfr * hr - gfi * hi;
        }
    }

    // tail sum S = Σ_c lam_b^{CLEN*c} * partial_c
    const float ab = expf(bnu[d]);
    const float thb = btheta[d];
    const float rb = expf(-ab);
    float sb, cb;
    sincosf(thb, &sb, &cb);
    const float lbr = rb * cb, lbi = rb * sb;
    const float gbr = bgr[d], gbi = bgi[d];

    float Sr = 0.f, Si = 0.f;
#pragma unroll
    for (int c = 0; c < NCHUNK; c++) {
        const float t = (float)(CLEN * c);
        const float e = expf(-t * ab);
        float sw, cw;
        sincosf(t * thb, &sw, &cw);
        const float wr = e * cw, wi = e * sw;
        const float pr = g_pr[(b * NCHUNK + c) * Dq + d];
        const float pi = g_pi[(b * NCHUNK + c) * Dq + d];
        Sr += wr * pr - wi * pi;
        Si += wr * pi + wi * pr;
    }

    // backward scan seeded with S
    float hr = Sr, hi = Si;
#pragma unroll
    for (int t = Pq - 1; t >= 0; t--) {
        float nr = fmaf(lbr, hr, fmaf(-lbi, hi, x[t]));
        float ni = fmaf(lbr, hi, lbi * hr);
        hr = nr; hi = ni;
        yc[t * (2 * Dq) + Dq + d] = gbr * hr - gbi * hi;
    }
}

// ---------------------------------------------------------------------------
// Kernel 3a: split-K partial projection.
// Block = (row-group of 8, k-split of 128, batch). 256 threads = j.
// Y tile staged in smem [k][p]; Wt streamed coalesced (high MLP).
// ---------------------------------------------------------------------------
__global__ void __launch_bounds__(256) k_proj_part() {
    __shared__ float ys[KSEG * RG];   // [k][p]
    const int j  = threadIdx.x;
    const int p0 = blockIdx.x * RG;
    const int k0 = blockIdx.y * KSEG;
    const int b  = blockIdx.z;

    const float* src = g_ycat + (size_t)(b * Pq + p0) * (2 * Dq) + k0;
#pragma unroll
    for (int it = 0; it < (KSEG * RG) / 256; it++) {
        int idx = j + it * 256;
        int p = idx >> 7;          // KSEG == 128
        int k = idx & (KSEG - 1);
        ys[k * RG + p] = src[p * (2 * Dq) + k];
    }
    __syncthreads();

    float a0 = 0.f, a1 = 0.f, a2 = 0.f, a3 = 0.f;
    float a4 = 0.f, a5 = 0.f, a6 = 0.f, a7 = 0.f;
    const float* wp = g_Wt + (size_t)k0 * Dq + j;
#pragma unroll 4
    for (int k = 0; k < KSEG; k++) {
        const float w = wp[k * Dq];
        const float4 y0 = *(const float4*)&ys[k * RG];
        const float4 y1 = *(const float4*)&ys[k * RG + 4];
        a0 = fmaf(y0.x, w, a0);
        a1 = fmaf(y0.y, w, a1);
        a2 = fmaf(y0.z, w, a2);
        a3 = fmaf(y0.w, w, a3);
        a4 = fmaf(y1.x, w, a4);
        a5 = fmaf(y1.y, w, a5);
        a6 = fmaf(y1.z, w, a6);
        a7 = fmaf(y1.w, w, a7);
    }

    float* o = g_part + ((size_t)(b * KSPLIT + blockIdx.y) * Pq + p0) * Dq + j;
    o[0 * Dq] = a0;
    o[1 * Dq] = a1;
    o[2 * Dq] = a2;
    o[3 * Dq] = a3;
    o[4 * Dq] = a4;
    o[5 * Dq] = a5;
    o[6 * Dq] = a6;
    o[7 * Dq] = a7;
}

// ---------------------------------------------------------------------------
// Kernel 3b: reduce split-k partials + bias -> out
// ---------------------------------------------------------------------------
__global__ void k_reduce(const float* __restrict__ bias, float* __restrict__ out) {
    const int j   = threadIdx.x;
    const int row = blockIdx.x;        // b*Pq + p
    const int b   = row >> 6;
    const int p   = row & (Pq - 1);

    float s = bias[j];
#pragma unroll
    for (int ks = 0; ks < KSPLIT; ks++)
        s += g_part[((size_t)(b * KSPLIT + ks) * Pq + p) * Dq + j];
    out[(size_t)row * Dq + j] = s;
}

// ---------------------------------------------------------------------------
extern "C" void kernel_launch(void* const* d_in, const int* in_sizes, int n_in,
                              void* d_out, int out_size) {
    const float* memory  = (const float*)d_in[0];
    const float* ts      = (const float*)d_in[1];
    const float* fnu     = (const float*)d_in[2];
    const float* ftheta  = (const float*)d_in[3];
    const float* fgr     = (const float*)d_in[4];
    const float* fgi     = (const float*)d_in[5];
    const float* bnu     = (const float*)d_in[6];
    const float* btheta  = (const float*)d_in[7];
    const float* bgr     = (const float*)d_in[8];
    const float* bgi     = (const float*)d_in[9];
    const float* projW   = (const float*)d_in[10];
    const float* projb   = (const float*)d_in[11];
    const float* prefix  = (const float*)d_in[12];
    const float* signal  = (const float*)d_in[13];
    float* out = (float*)d_out;

    k_transpose<<<2 * Dq, Dq>>>(projW);
    k_chunks<<<dim3(NCHUNK, Bq), Dq>>>(ts, bnu, btheta, signal);
    k_scan<<<Bq, Dq>>>(memory, fnu, ftheta, fgr, fgi,
                       bnu, btheta, bgr, bgi, prefix);
    k_proj_part<<<dim3(Pq / RG, KSPLIT, Bq), Dq>>>();
    k_reduce<<<Bq * Pq, Dq>>>(projb, out);
}